// round 1
// baseline (speedup 1.0000x reference)
#include <cuda_runtime.h>
#include <math.h>

#define NGR    256   // graphs (= grid)
#define NPG_   256   // nodes per graph
#define FDIM   128
#define EPG    4096  // edges per graph (contiguous!)
#define DLAT   97
#define KTOP   30
#define C1_    16
#define C2_    32
#define T2_    11
#define DENSE_ 352

// shared memory layout (floats)
//  h1 0, h2 8192, h3 16384, g 24576, z4 32768, invd 33024,
//  Ws 33280 (4096), bs 37376 (32), scratch 37408 (8192),
//  offs(int) @45600 (257), cnt(int) (256), elist(u16) 4096
#define SM_FLOATS 48161
static const int SMEM_BYTES = SM_FLOATS * 4;

__global__ __launch_bounds__(256, 1)
void dgcnn_kernel(const float* __restrict__ nf,
                  const int* __restrict__ src, const int* __restrict__ dst,
                  const int* __restrict__ degs,
                  const float* __restrict__ W0, const float* __restrict__ b0,
                  const float* __restrict__ W1, const float* __restrict__ b1,
                  const float* __restrict__ W2, const float* __restrict__ b2,
                  const float* __restrict__ W3, const float* __restrict__ b3,
                  const float* __restrict__ c1w, const float* __restrict__ c1b,
                  const float* __restrict__ c2w, const float* __restrict__ c2b,
                  const float* __restrict__ ow, const float* __restrict__ ob,
                  float* __restrict__ out)
{
    extern __shared__ float sm[];
    float* h1      = sm;
    float* h2      = h1 + 8192;
    float* h3      = h2 + 8192;
    float* g       = h3 + 8192;
    float* z4      = g  + 8192;
    float* invd    = z4 + 256;
    float* Ws      = invd + 256;
    float* bs      = Ws + 4096;
    float* scratch = bs + 32;                 // 8192 floats, multi-purpose
    int*   offs    = (int*)(scratch + 8192);  // 257
    int*   cnt     = offs + 257;              // 256 (reused as selrow)
    unsigned short* elist = (unsigned short*)(cnt + 256);  // 4096

    const int b    = blockIdx.x;
    const int t    = threadIdx.x;
    const int w    = t >> 5;
    const int lane = t & 31;
    const int base = b * NPG_;

    // ---------- init: degrees, inv(deg+1), W0/b0 staging ----------
    {
        int d = degs[base + t];
        cnt[t]  = d;
        invd[t] = 1.0f / ((float)d + 1.0f);
    }
    for (int i = t; i < FDIM * 32; i += 256) Ws[i] = W0[i];
    if (t < 32) bs[t] = b0[t];
    __syncthreads();

    if (t == 0) {
        int s = 0;
        for (int i = 0; i < 256; i++) { offs[i] = s; s += cnt[i]; }
        offs[256] = s;   // == EPG
    }
    __syncthreads();
    cnt[t] = offs[t];
    __syncthreads();

    // ---------- build in-edge CSR (local u16 src ids) ----------
    for (int i = t; i < EPG; i += 256) {
        int e  = b * EPG + i;
        int ls = src[e] - base;
        int ld = dst[e] - base;
        int pos = atomicAdd(&cnt[ld], 1);
        elist[pos] = (unsigned short)ls;
    }
    __syncthreads();

    // ---------- Layer 0 GEMM: g = node_feat @ W0, 64-node chunks ----------
    for (int chunk = 0; chunk < 4; chunk++) {
        const float4* src4 = (const float4*)(nf + (size_t)(base + chunk * 64) * FDIM);
        float4* dst4 = (float4*)scratch;
        for (int i = t; i < 64 * FDIM / 4; i += 256) dst4[i] = src4[i];
        __syncthreads();

        float acc[8];
#pragma unroll
        for (int i = 0; i < 8; i++) acc[i] = 0.f;
#pragma unroll
        for (int k0 = 0; k0 < FDIM; k0 += 16) {
            float wr[16];
#pragma unroll
            for (int kk = 0; kk < 16; kk++) wr[kk] = Ws[(k0 + kk) * 32 + lane];
#pragma unroll
            for (int i = 0; i < 8; i++) {
                const float* row = scratch + (w * 8 + i) * FDIM + k0;
#pragma unroll
                for (int kk = 0; kk < 16; kk++)
                    acc[i] = fmaf(row[kk], wr[kk], acc[i]);
            }
        }
#pragma unroll
        for (int i = 0; i < 8; i++)
            g[(chunk * 64 + w * 8 + i) * 32 + lane] = acc[i];
        __syncthreads();
    }

    // ---------- Layer 0 aggregate + tanh -> h1 ----------
#pragma unroll 1
    for (int nn = 0; nn < 32; nn++) {
        int n = w * 32 + nn;
        float acc = g[n * 32 + lane];
        int beg = offs[n], end = offs[n + 1];
        for (int j = beg; j < end; j++)
            acc += g[(int)elist[j] * 32 + lane];
        h1[n * 32 + lane] = tanhf((acc + bs[lane]) * invd[n]);
    }
    __syncthreads();

    // ---------- Layers 1,2 (32->32) ----------
    {
        const float* Wg[2] = {W1, W2};
        const float* bg[2] = {b1, b2};
        float* hin = h1;
        float* houts[2] = {h2, h3};
        for (int L = 0; L < 2; L++) {
            for (int i = t; i < 1024; i += 256) Ws[i] = Wg[L][i];
            if (t < 32) bs[t] = bg[L][t];
            __syncthreads();

            float wr[32];
#pragma unroll
            for (int k = 0; k < 32; k++) wr[k] = Ws[k * 32 + lane];
#pragma unroll 1
            for (int nn = 0; nn < 32; nn++) {
                int n = w * 32 + nn;
                const float* row = hin + n * 32;
                float acc = 0.f;
#pragma unroll
                for (int k = 0; k < 32; k++) acc = fmaf(row[k], wr[k], acc);
                g[n * 32 + lane] = acc;
            }
            __syncthreads();

            float* hout = houts[L];
#pragma unroll 1
            for (int nn = 0; nn < 32; nn++) {
                int n = w * 32 + nn;
                float acc = g[n * 32 + lane];
                int beg = offs[n], end = offs[n + 1];
                for (int j = beg; j < end; j++)
                    acc += g[(int)elist[j] * 32 + lane];
                hout[n * 32 + lane] = tanhf((acc + bs[lane]) * invd[n]);
            }
            __syncthreads();
            hin = hout;
        }
    }

    // ---------- Layer 3 (32->1) -> z4 ----------
    {
        float* g1  = scratch;     // 256 floats
        float w3r  = W3[lane];
        float b3v  = b3[0];
#pragma unroll 1
        for (int nn = 0; nn < 32; nn++) {
            int n = w * 32 + nn;
            float v = h3[n * 32 + lane] * w3r;
#pragma unroll
            for (int off = 16; off; off >>= 1)
                v += __shfl_xor_sync(0xffffffffu, v, off);
            if (lane == 0) g1[n] = v;
        }
        __syncthreads();
        {
            float acc = g1[t];
            for (int j = offs[t]; j < offs[t + 1]; j++)
                acc += g1[(int)elist[j]];
            z4[t] = tanhf((acc + b3v) * invd[t]);
        }
        __syncthreads();
    }

    // ---------- sortpool: rank = #{j : v_j > v_i or (==, j<i)} ----------
    int* selrow = cnt;   // reuse
    {
        float v = z4[t];
        int r = 0;
        for (int j = 0; j < 256; j++) {
            float u = z4[j];
            r += (int)((u > v) || (u == v && j < t));
        }
        if (r < KTOP) selrow[r] = t;
    }
    __syncthreads();

    // ---------- gather sp[30][97] ----------
    float* sp = scratch;         // overwrites g1 (dead)
    for (int i = t; i < KTOP * DLAT; i += 256) {
        int k = i / DLAT, d = i - k * DLAT;
        int n = selrow[k];
        float v;
        if (d < 32)      v = h1[n * 32 + d];
        else if (d < 64) v = h2[n * 32 + d - 32];
        else if (d < 96) v = h3[n * 32 + d - 64];
        else             v = z4[n];
        sp[i] = v;
    }
    __syncthreads();

    // ---------- conv1 (stride D) + relu -> out1[16][30] ----------
    float* out1 = scratch + 3000;
    for (int i = t; i < C1_ * KTOP; i += 256) {
        int c = i & 15, k = i >> 4;
        float acc = c1b[c];
        const float* wr = c1w + c * DLAT;
        const float* sr = sp + k * DLAT;
        for (int d = 0; d < DLAT; d++) acc = fmaf(sr[d], wr[d], acc);
        out1[c * KTOP + k] = fmaxf(acc, 0.f);
    }
    __syncthreads();

    // ---------- maxpool(2,2) -> pool[16][15] ----------
    float* pool = scratch + 3500;
    for (int i = t; i < C1_ * 15; i += 256) {
        int c = i / 15, tt = i - c * 15;
        pool[i] = fmaxf(out1[c * KTOP + 2 * tt], out1[c * KTOP + 2 * tt + 1]);
    }
    __syncthreads();

    // ---------- conv2 (kw=5) + relu -> out2[32][11] ----------
    float* out2 = scratch + 3800;
    for (int i = t; i < C2_ * T2_; i += 256) {
        int c2 = i / T2_, tt = i - c2 * T2_;
        float acc = c2b[c2];
#pragma unroll
        for (int c1 = 0; c1 < C1_; c1++) {
            const float* wv = c2w + (c2 * C1_ + c1) * 5;
            const float* pv = pool + c1 * 15 + tt;
#pragma unroll
            for (int j = 0; j < 5; j++) acc = fmaf(pv[j], wv[j], acc);
        }
        out2[i] = fmaxf(acc, 0.f);
    }
    __syncthreads();

    // ---------- dense [352]x[352,2] + relu (relu twice == once) ----------
    if (w == 0) {
        float a0 = 0.f, a1 = 0.f;
        for (int i = lane; i < DENSE_; i += 32) {
            float x = out2[i];
            a0 = fmaf(x, ow[i * 2 + 0], a0);
            a1 = fmaf(x, ow[i * 2 + 1], a1);
        }
#pragma unroll
        for (int off = 16; off; off >>= 1) {
            a0 += __shfl_xor_sync(0xffffffffu, a0, off);
            a1 += __shfl_xor_sync(0xffffffffu, a1, off);
        }
        if (lane == 0) {
            out[b * 2 + 0] = fmaxf(a0 + ob[0], 0.f);
            out[b * 2 + 1] = fmaxf(a1 + ob[1], 0.f);
        }
    }
}

extern "C" void kernel_launch(void* const* d_in, const int* in_sizes, int n_in,
                              void* d_out, int out_size)
{
    // Detect input ordering:
    //  (a) setup_inputs dict order: node_feat, src, dst, degs, W0,b0,...,out_b
    //  (b) reference signature order: node_feat, W0,b0,...,out_b, src, dst, degs
    int iSrc, iDst, iDeg, iW0, ib0, iW1, ib1, iW2, ib2, iW3, ib3;
    int ic1w, ic1b, ic2w, ic2b, iow, iob;
    if (n_in > 1 && in_sizes[1] == NGR * EPG) {
        iSrc = 1; iDst = 2; iDeg = 3;
        iW0 = 4;  ib0 = 5;  iW1 = 6;  ib1 = 7;
        iW2 = 8;  ib2 = 9;  iW3 = 10; ib3 = 11;
        ic1w = 12; ic1b = 13; ic2w = 14; ic2b = 15; iow = 16; iob = 17;
    } else {
        iW0 = 1;  ib0 = 2;  iW1 = 3;  ib1 = 4;
        iW2 = 5;  ib2 = 6;  iW3 = 7;  ib3 = 8;
        ic1w = 9; ic1b = 10; ic2w = 11; ic2b = 12; iow = 13; iob = 14;
        iSrc = 15; iDst = 16; iDeg = 17;
    }

    cudaFuncSetAttribute(dgcnn_kernel,
                         cudaFuncAttributeMaxDynamicSharedMemorySize, SMEM_BYTES);

    dgcnn_kernel<<<NGR, 256, SMEM_BYTES>>>(
        (const float*)d_in[0],
        (const int*)d_in[iSrc], (const int*)d_in[iDst], (const int*)d_in[iDeg],
        (const float*)d_in[iW0], (const float*)d_in[ib0],
        (const float*)d_in[iW1], (const float*)d_in[ib1],
        (const float*)d_in[iW2], (const float*)d_in[ib2],
        (const float*)d_in[iW3], (const float*)d_in[ib3],
        (const float*)d_in[ic1w], (const float*)d_in[ic1b],
        (const float*)d_in[ic2w], (const float*)d_in[ic2b],
        (const float*)d_in[iow], (const float*)d_in[iob],
        (float*)d_out);
}